// round 2
// baseline (speedup 1.0000x reference)
#include <cuda_runtime.h>
#include <mma.h>

using namespace nvcuda;

typedef unsigned long long ull;

// Problem constants
#define B_   16
#define T_   1024
#define DIN  1024
#define UN   512
#define NG   2048          // 4*U
#define M_   (B_ * T_)     // 16384
#define NL   5

// ---------------- scratch (static __device__, allocation-free) -------------
__device__ float g_xz[2][(size_t)M_ * NG];     // per-dir input projections (256MB)
__device__ float g_yb[2][(size_t)M_ * DIN];    // layer output ping-pong (128MB)
__device__ float g_h[2][2][UN * B_];           // h state ping-pong per dir, layout [unit][b]
__device__ unsigned g_cnt[2];
__device__ unsigned g_gen[2];

// ---------------- small helpers --------------------------------------------
__device__ __forceinline__ float sigm(float x) {
    return 1.0f / (1.0f + __expf(-x));
}

__device__ __forceinline__ ull fma2(ull a, ull b, ull c) {
    ull d;
    asm("fma.rn.f32x2 %0, %1, %2, %3;" : "=l"(d) : "l"(a), "l"(b), "l"(c));
    return d;
}
__device__ __forceinline__ ull add2(ull a, ull b) {
    ull d;
    asm("add.rn.f32x2 %0, %1, %2;" : "=l"(d) : "l"(a), "l"(b));
    return d;
}
__device__ __forceinline__ ull dup2(float u) {
    ull d;
    unsigned uu = __float_as_uint(u);
    asm("mov.b64 %0, {%1, %1};" : "=l"(d) : "r"(uu));
    return d;
}

// Inter-CTA barrier among the 64 CTAs of one direction.
// Release: __syncthreads + cumulative __threadfence + atomic. Acquire: ld.acquire.gpu spin.
__device__ __forceinline__ void dir_barrier(int d, unsigned tgt) {
    __syncthreads();
    if (threadIdx.x == 0) {
        __threadfence();
        unsigned prev = atomicAdd(&g_cnt[d], 1u);
        if (prev == 63u) {
            g_cnt[d] = 0u;
            __threadfence();
            atomicAdd(&g_gen[d], 1u);
        } else {
            unsigned v;
            do {
                asm volatile("ld.acquire.gpu.u32 %0, [%1];" : "=r"(v)
                             : "l"((const unsigned*)&g_gen[d]) : "memory");
            } while ((int)(v - tgt) < 0);
        }
    }
    __syncthreads();
}

// ---------------- input-projection GEMM (TF32 wmma) -------------------------
// C[M_, NG] = A[M_, DIN] @ W[DIN, NG] + bias ; grid.z = direction
#define BM 128
#define BN 128
#define BK 16
#define AP 24    // As leading dim (pad)
#define BP 136   // Bs / bias leading dim (pad)

__global__ void __launch_bounds__(256) lstm_gemm(const float* __restrict__ xin, int a_sel,
                                                 const float* __restrict__ Wl,
                                                 const float* __restrict__ bl) {
    __shared__ float As[BM * AP];
    __shared__ float Bs[BK * BP];
    __shared__ float Bias[16 * BP];

    const int d = blockIdx.z;
    const float* A = (a_sel == 0) ? xin : g_yb[a_sel - 1];
    const float* W = Wl + (size_t)d * DIN * NG;
    const float* bias = bl + d * NG;
    float* C = g_xz[d];

    const int tid = threadIdx.x;
    const int bn0 = blockIdx.x * BN;
    const int bm0 = blockIdx.y * BM;

    // bias tile (16 identical rows so we can init accumulators from it)
    for (int i = tid; i < 16 * BN; i += 256) {
        int r = i >> 7, c = i & 127;
        Bias[r * BP + c] = bias[bn0 + c];
    }
    __syncthreads();

    const int wid = tid >> 5;
    const int wr = wid >> 2;   // 0..1  -> 64-row slab
    const int wc = wid & 3;    // 0..3  -> 32-col slab

    wmma::fragment<wmma::accumulator, 16, 16, 8, float> acc[4][2];
#pragma unroll
    for (int mm = 0; mm < 4; ++mm)
#pragma unroll
        for (int nn = 0; nn < 2; ++nn)
            wmma::load_matrix_sync(acc[mm][nn], &Bias[wc * 32 + nn * 16], BP,
                                   wmma::mem_row_major);

    for (int kt = 0; kt < DIN / BK; ++kt) {
#pragma unroll
        for (int i = 0; i < 2; ++i) {
            int id = tid + i * 256;
            int r = id >> 2, c4 = (id & 3) << 2;
            *(float4*)&As[r * AP + c4] =
                *(const float4*)&A[(size_t)(bm0 + r) * DIN + kt * BK + c4];
        }
#pragma unroll
        for (int i = 0; i < 2; ++i) {
            int id = tid + i * 256;
            int r = id >> 5, c4 = (id & 31) << 2;
            *(float4*)&Bs[r * BP + c4] =
                *(const float4*)&W[(size_t)(kt * BK + r) * NG + bn0 + c4];
        }
        __syncthreads();

#pragma unroll
        for (int kk = 0; kk < 2; ++kk) {
            wmma::fragment<wmma::matrix_a, 16, 16, 8, wmma::precision::tf32,
                           wmma::row_major> af[4];
            wmma::fragment<wmma::matrix_b, 16, 16, 8, wmma::precision::tf32,
                           wmma::row_major> bf[2];
#pragma unroll
            for (int mm = 0; mm < 4; ++mm) {
                wmma::load_matrix_sync(af[mm], &As[(wr * 64 + mm * 16) * AP + kk * 8], AP);
#pragma unroll
                for (int e = 0; e < af[mm].num_elements; ++e)
                    af[mm].x[e] = wmma::__float_to_tf32(af[mm].x[e]);
            }
#pragma unroll
            for (int nn = 0; nn < 2; ++nn) {
                wmma::load_matrix_sync(bf[nn], &Bs[kk * 8 * BP + wc * 32 + nn * 16], BP);
#pragma unroll
                for (int e = 0; e < bf[nn].num_elements; ++e)
                    bf[nn].x[e] = wmma::__float_to_tf32(bf[nn].x[e]);
            }
#pragma unroll
            for (int mm = 0; mm < 4; ++mm)
#pragma unroll
                for (int nn = 0; nn < 2; ++nn)
                    wmma::mma_sync(acc[mm][nn], af[mm], bf[nn], acc[mm][nn]);
        }
        __syncthreads();
    }

#pragma unroll
    for (int mm = 0; mm < 4; ++mm)
#pragma unroll
        for (int nn = 0; nn < 2; ++nn)
            wmma::store_matrix_sync(
                &C[(size_t)(bm0 + wr * 64 + mm * 16) * NG + bn0 + wc * 32 + nn * 16],
                acc[mm][nn], NG, wmma::mem_row_major);
}

// ---------------- persistent bidirectional recurrence ----------------------
// 128 CTAs: blocks 0..63 dir 0 (forward), 64..127 dir 1 (reverse).
// Each CTA owns 8 units -> 32 gate columns; Uh slice resident in SMEM.
// SMEM layout (dynamic):
#define OFF_UH   0                       // float[512*32]      65536 B
#define OFF_HS   65536                   // float[512*16]      32768 B
#define OFF_RED  98304                   // ull[8*32*8]        16384 B
#define OFF_XZ   114688                  // ull[32*8]           2048 B
#define OFF_ZZ   116736                  // ull[32*8]           2048 B
#define OFF_CS   118784                  // float[128]           512 B
#define OFF_GEN  119296                  // unsigned
#define REC_SMEM 119424

__global__ void __launch_bounds__(256, 1) lstm_rec(const float* __restrict__ Uh_l,
                                                   int y_sel, float* __restrict__ out) {
    extern __shared__ char sm[];
    float* Uh_s = (float*)(sm + OFF_UH);
    float* h_s  = (float*)(sm + OFF_HS);
    ull*   red  = (ull*)(sm + OFF_RED);
    ull*   xz_s = (ull*)(sm + OFF_XZ);
    ull*   zz_s = (ull*)(sm + OFF_ZZ);
    float* c_s  = (float*)(sm + OFF_CS);
    unsigned* s_gen0 = (unsigned*)(sm + OFF_GEN);

    const int tid = threadIdx.x;
    const int d = blockIdx.x >> 6;
    const int cb = blockIdx.x & 63;
    const int u0 = cb * 8;

    const float* Uh = Uh_l + (size_t)d * UN * NG;
    const float* xz = g_xz[d];
    float* yout = (y_sel == 0) ? g_yb[0] : (y_sel == 1 ? g_yb[1] : out);

    // load this CTA's Uh slice: smem col c = g*8+j  <->  global col g*512 + u0 + j
    for (int i = tid; i < UN * 32; i += 256) {
        int k = i >> 5, c = i & 31;
        int g = c >> 3, j = c & 7;
        Uh_s[i] = Uh[(size_t)k * NG + g * UN + u0 + j];
    }
    if (tid < 128) {
        c_s[tid] = 0.0f;
        int ul = tid >> 4, b = tid & 15;
        g_h[d][0][(u0 + ul) * B_ + b] = 0.0f;   // zero initial h (own units)
    }
    if (tid == 0) {
        unsigned v;
        asm volatile("ld.acquire.gpu.u32 %0, [%1];" : "=r"(v)
                     : "l"((const unsigned*)&g_gen[d]));
        *s_gen0 = v;
    }
    __syncthreads();
    unsigned tgt = *s_gen0 + 1;
    dir_barrier(d, tgt);   // make all zero-inits visible
    ++tgt;

    const int wid = tid >> 5, lane = tid & 31;
    const int k0 = wid << 6;     // 64-wide K chunk per warp

    for (int step = 0; step < T_; ++step) {
        const int tt = d ? (T_ - 1 - step) : step;

        // 1) prefetch xz for this timestep -> xz_s[c][b]
        {
            int b = tid >> 4, q = tid & 15;
            int g = q >> 2, jj = (q & 3) << 1;
            float2 v = *(const float2*)&xz[((size_t)(b << 10) + tt) * NG + g * UN + u0 + jj];
            float* xzf = (float*)xz_s;
            int c = g * 8 + jj;
            xzf[c * B_ + b] = v.x;
            xzf[(c + 1) * B_ + b] = v.y;
        }
        // 2) stage full h_prev into smem (L2-fresh: bypass L1)
        {
            const float4* src = (const float4*)&g_h[d][step & 1][0];
            float4* dst = (float4*)h_s;
#pragma unroll
            for (int i = 0; i < 8; ++i) dst[tid + i * 256] = __ldcg(src + tid + i * 256);
        }
        __syncthreads();

        // 3) dot products: lane = column, acc over 16 batches packed as 8 f32x2
        ull a0 = 0, a1 = 0, a2 = 0, a3 = 0, a4 = 0, a5 = 0, a6 = 0, a7 = 0;
        const ulonglong2* hb = (const ulonglong2*)h_s;
#pragma unroll 8
        for (int k = k0; k < k0 + 64; ++k) {
            ull up = dup2(Uh_s[(k << 5) + lane]);
            ulonglong2 q0 = hb[k * 4 + 0];
            ulonglong2 q1 = hb[k * 4 + 1];
            ulonglong2 q2 = hb[k * 4 + 2];
            ulonglong2 q3 = hb[k * 4 + 3];
            a0 = fma2(q0.x, up, a0);  a1 = fma2(q0.y, up, a1);
            a2 = fma2(q1.x, up, a2);  a3 = fma2(q1.y, up, a3);
            a4 = fma2(q2.x, up, a4);  a5 = fma2(q2.y, up, a5);
            a6 = fma2(q3.x, up, a6);  a7 = fma2(q3.y, up, a7);
        }
        {
            ulonglong2* rr = (ulonglong2*)(red + tid * 8);
            rr[0] = make_ulonglong2(a0, a1);
            rr[1] = make_ulonglong2(a2, a3);
            rr[2] = make_ulonglong2(a4, a5);
            rr[3] = make_ulonglong2(a6, a7);
        }
        __syncthreads();

        // 4) reduce 8 warp-partials + xz  ->  zz_s
        {
            int c = tid >> 3, p = tid & 7;
            ull v = xz_s[c * 8 + p];
#pragma unroll
            for (int w = 0; w < 8; ++w) v = add2(v, red[(w * 32 + c) * 8 + p]);
            zz_s[c * 8 + p] = v;
        }
        __syncthreads();

        // 5) gates + state update + outputs
        if (tid < 128) {
            int ul = tid >> 4, b = tid & 15;
            const float* zzf = (const float*)zz_s;
            float zi = zzf[(0 * 8 + ul) * B_ + b];
            float zf = zzf[(1 * 8 + ul) * B_ + b];
            float zg = zzf[(2 * 8 + ul) * B_ + b];
            float zo = zzf[(3 * 8 + ul) * B_ + b];
            float fi = sigm(zi), ff = sigm(zf), fg = sigm(zg), fo = sigm(zo);
            float cc = ff * c_s[tid] + fi * fg;
            c_s[tid] = cc;
            float h = fo * sigm(cc);
            g_h[d][(step & 1) ^ 1][(u0 + ul) * B_ + b] = h;
            yout[((size_t)(b << 10) + tt) * (2 * UN) + (d << 9) + u0 + ul] = h;
        }

        if (step != T_ - 1) {
            dir_barrier(d, tgt);
            ++tgt;
        }
    }
}

// ---------------- launcher ---------------------------------------------------
extern "C" void kernel_launch(void* const* d_in, const int* in_sizes, int n_in,
                              void* d_out, int out_size) {
    (void)in_sizes; (void)n_in; (void)out_size;
    const float* x  = (const float*)d_in[0];
    const float* W  = (const float*)d_in[1];
    const float* Uh = (const float*)d_in[2];
    const float* bb = (const float*)d_in[3];
    float* out = (float*)d_out;

    cudaFuncSetAttribute(lstm_rec, cudaFuncAttributeMaxDynamicSharedMemorySize, REC_SMEM);

    dim3 ggrid(NG / BN, M_ / BM, 2);
    for (int l = 0; l < NL; ++l) {
        int a_sel = (l == 0) ? 0 : 1 + ((l - 1) & 1);
        lstm_gemm<<<ggrid, 256>>>(x, a_sel,
                                  W + (size_t)l * 2 * DIN * NG,
                                  bb + (size_t)l * 2 * NG);
        int y_sel = (l == NL - 1) ? 2 : (l & 1);
        lstm_rec<<<128, 256, REC_SMEM>>>(Uh + (size_t)l * 2 * UN * NG, y_sel, out);
    }
}

// round 3
// speedup vs baseline: 1.1398x; 1.1398x over previous
#include <cuda_runtime.h>
#include <mma.h>

using namespace nvcuda;

typedef unsigned long long ull;

// Problem constants
#define B_   16
#define T_   1024
#define DIN  1024
#define UN   512
#define NG   2048          // 4*U
#define M_   (B_ * T_)     // 16384
#define NL   5

// ---------------- scratch (static __device__, allocation-free) -------------
__device__ float g_xz[2][(size_t)M_ * NG];     // per-dir input projections
__device__ float g_yb[2][(size_t)M_ * DIN];    // layer output ping-pong
__device__ float g_h[2][2][UN * B_];           // h state ping-pong per dir [unit][b]
__device__ unsigned g_flag[2][64];             // per-CTA monotonic step flags

// ---------------- small helpers --------------------------------------------
__device__ __forceinline__ float sigm(float x) {
    return 1.0f / (1.0f + __expf(-x));
}
__device__ __forceinline__ float tf32r(float x) {
    unsigned u;
    asm("cvt.rna.tf32.f32 %0, %1;" : "=r"(u) : "f"(x));
    return __uint_as_float(u);
}
__device__ __forceinline__ void cp16(float* s, const float* g) {
    unsigned a = (unsigned)__cvta_generic_to_shared(s);
    asm volatile("cp.async.cg.shared.global [%0], [%1], 16;" :: "r"(a), "l"(g));
}
__device__ __forceinline__ void cp_commit() {
    asm volatile("cp.async.commit_group;" ::: "memory");
}
__device__ __forceinline__ void cp_wait0() {
    asm volatile("cp.async.wait_group 0;" ::: "memory");
}
__device__ __forceinline__ unsigned ld_acq(const unsigned* p) {
    unsigned v;
    asm volatile("ld.acquire.gpu.u32 %0, [%1];" : "=r"(v) : "l"(p) : "memory");
    return v;
}
__device__ __forceinline__ void st_rel(unsigned* p, unsigned v) {
    asm volatile("st.release.gpu.u32 [%0], %1;" :: "l"(p), "r"(v) : "memory");
}

// ---------------- input-projection GEMM (TF32 wmma, cp.async pipelined) ----
// C[M_, NG] = A[M_, DIN] @ W[DIN, NG] + bias ; grid.z = direction
#define BM 128
#define BN 128
#define BK 32
#define AP 36    // As leading dim (floats): 144B, 16B multiple
#define BP 136   // Bs / bias leading dim:   544B, 16B multiple
#define ASZ (BM * AP)   // 4608 floats per buffer
#define BSZ (BK * BP)   // 4352 floats per buffer
#define GEMM_SMEM ((2 * ASZ + 2 * BSZ + 16 * BP) * 4)  // 80384 B

__global__ void __launch_bounds__(256, 2) lstm_gemm(const float* __restrict__ xin, int a_sel,
                                                    const float* __restrict__ Wl,
                                                    const float* __restrict__ bl) {
    extern __shared__ float gsm[];
    float* As = gsm;                       // 2 buffers
    float* Bs = gsm + 2 * ASZ;             // 2 buffers
    float* Bias = gsm + 2 * ASZ + 2 * BSZ; // 16 x BP

    const int d = blockIdx.z;
    const float* A = (a_sel == 0) ? xin : g_yb[a_sel - 1];
    const float* W = Wl + (size_t)d * DIN * NG;
    const float* bias = bl + d * NG;
    float* C = g_xz[d];

    const int tid = threadIdx.x;
    const int bn0 = blockIdx.x * BN;
    const int bm0 = blockIdx.y * BM;

    // bias tile (16 identical rows -> init accumulators from it)
    for (int i = tid; i < 16 * BN; i += 256) {
        int r = i >> 7, c = i & 127;
        Bias[r * BP + c] = bias[bn0 + c];
    }

    const int wid = tid >> 5;
    const int wr = wid >> 2;   // 0..1 -> 64-row slab
    const int wc = wid & 3;    // 0..3 -> 32-col slab

    const float* Abase = A + (size_t)bm0 * DIN;
    const float* Bbase = W + bn0;

    // tile loader (cp.async)
    auto issue = [&](int kt, int buf) {
        float* Ad = As + buf * ASZ;
        const float* Ag = Abase + kt * BK;
#pragma unroll
        for (int i = 0; i < 4; ++i) {
            int id = tid + i * 256;
            int r = id >> 3, c4 = (id & 7) << 2;
            cp16(&Ad[r * AP + c4], &Ag[(size_t)r * DIN + c4]);
        }
        float* Bd = Bs + buf * BSZ;
        const float* Bg = Bbase + (size_t)kt * BK * NG;
#pragma unroll
        for (int i = 0; i < 4; ++i) {
            int id = tid + i * 256;
            int r = id >> 5, c4 = (id & 31) << 2;
            cp16(&Bd[r * BP + c4], &Bg[(size_t)r * NG + c4]);
        }
        cp_commit();
    };

    issue(0, 0);
    __syncthreads();   // Bias visible

    wmma::fragment<wmma::accumulator, 16, 16, 8, float> acc[4][2];
#pragma unroll
    for (int mm = 0; mm < 4; ++mm)
#pragma unroll
        for (int nn = 0; nn < 2; ++nn)
            wmma::load_matrix_sync(acc[mm][nn], &Bias[wc * 32 + nn * 16], BP,
                                   wmma::mem_row_major);

    int buf = 0;
    const int NT = DIN / BK;   // 32
    for (int kt = 0; kt < NT; ++kt) {
        cp_wait0();
        __syncthreads();
        if (kt + 1 < NT) issue(kt + 1, buf ^ 1);

        float* Ab = As + buf * ASZ;
        float* Bb = Bs + buf * BSZ;
#pragma unroll
        for (int kk = 0; kk < 4; ++kk) {
            wmma::fragment<wmma::matrix_a, 16, 16, 8, wmma::precision::tf32,
                           wmma::row_major> af[4];
            wmma::fragment<wmma::matrix_b, 16, 16, 8, wmma::precision::tf32,
                           wmma::row_major> bf[2];
#pragma unroll
            for (int mm = 0; mm < 4; ++mm) {
                wmma::load_matrix_sync(af[mm], &Ab[(wr * 64 + mm * 16) * AP + kk * 8], AP);
#pragma unroll
                for (int e = 0; e < af[mm].num_elements; ++e)
                    af[mm].x[e] = wmma::__float_to_tf32(af[mm].x[e]);
            }
#pragma unroll
            for (int nn = 0; nn < 2; ++nn) {
                wmma::load_matrix_sync(bf[nn], &Bb[kk * 8 * BP + wc * 32 + nn * 16], BP);
#pragma unroll
                for (int e = 0; e < bf[nn].num_elements; ++e)
                    bf[nn].x[e] = wmma::__float_to_tf32(bf[nn].x[e]);
            }
#pragma unroll
            for (int mm = 0; mm < 4; ++mm)
#pragma unroll
                for (int nn = 0; nn < 2; ++nn)
                    wmma::mma_sync(acc[mm][nn], af[mm], bf[nn], acc[mm][nn]);
        }
        __syncthreads();
        buf ^= 1;
    }

#pragma unroll
    for (int mm = 0; mm < 4; ++mm)
#pragma unroll
        for (int nn = 0; nn < 2; ++nn)
            wmma::store_matrix_sync(
                &C[(size_t)(bm0 + wr * 64 + mm * 16) * NG + bn0 + wc * 32 + nn * 16],
                acc[mm][nn], NG, wmma::mem_row_major);
}

// ---------------- persistent bidirectional recurrence (tensor-core) --------
// 128 CTAs: blocks 0..63 dir 0 (fwd), 64..127 dir 1 (rev).
// Each CTA owns 8 units -> 32 gate columns. Uh slice lives in REGISTER
// fragments (loaded once); h broadcast through L2 with per-CTA release flags.
#define OFF_UH   0                       // float[512*32]   65536 B (init only)
#define OFF_HS   65536                   // float[512*16]   32768 B  A col-major
#define OFF_RED  98304                   // float[8*512]    16384 B  warp partials
#define OFF_XZ   114688                  // float[16*32]     2048 B  [b][c]
#define OFF_ZZ   116736                  // float[16*32]     2048 B  [b][c]
#define OFF_CS   118784                  // float[128]        512 B
#define REC_SMEM 119296

__global__ void __launch_bounds__(256, 1) lstm_rec(const float* __restrict__ Uh_l,
                                                   int y_sel, float* __restrict__ out) {
    extern __shared__ char sm[];
    float* Uh_s = (float*)(sm + OFF_UH);
    float* h_s  = (float*)(sm + OFF_HS);
    float* red  = (float*)(sm + OFF_RED);
    float* xz_s = (float*)(sm + OFF_XZ);
    float* zz_s = (float*)(sm + OFF_ZZ);
    float* c_s  = (float*)(sm + OFF_CS);

    const int tid = threadIdx.x;
    const int d = blockIdx.x >> 6;
    const int cb = blockIdx.x & 63;
    const int u0 = cb * 8;
    const int wid = tid >> 5;
    const int k0 = wid << 6;             // 64-wide K chunk per warp

    const float* Uh = Uh_l + (size_t)d * UN * NG;
    const float* xz = g_xz[d];
    float* yout = (y_sel == 0) ? g_yb[0] : (y_sel == 1 ? g_yb[1] : out);

    // monotonic flag base (flags uniform across launches by induction)
    const unsigned base = ld_acq(&g_flag[d][cb]);

    // Uh slice into smem (tf32-rounded): smem col c = g*8+j <-> global g*512+u0+j
    for (int i = tid; i < UN * 32; i += 256) {
        int k = i >> 5, c = i & 31;
        int g = c >> 3, j = c & 7;
        Uh_s[i] = tf32r(Uh[(size_t)k * NG + g * UN + u0 + j]);
    }
    if (tid < 128) {
        c_s[tid] = 0.0f;
        int ul = tid >> 4, b = tid & 15;
        g_h[d][0][(u0 + ul) * B_ + b] = 0.0f;   // zero initial h (own units)
    }
    __syncthreads();

    // register-resident Uh fragments: 8 k-steps x 2 n-tiles per warp
    wmma::fragment<wmma::matrix_b, 16, 16, 8, wmma::precision::tf32,
                   wmma::row_major> bf[8][2];
#pragma unroll
    for (int ks = 0; ks < 8; ++ks)
#pragma unroll
        for (int nt = 0; nt < 2; ++nt)
            wmma::load_matrix_sync(bf[ks][nt], &Uh_s[(k0 + ks * 8) * 32 + nt * 16], 32);

    __syncthreads();
    if (tid == 0) st_rel(&g_flag[d][cb], base + 1);   // zeros published

    for (int step = 0; step < T_; ++step) {
        const int tt = d ? (T_ - 1 - step) : step;

        // 1) xz load into regs (independent of flags -> overlaps the poll)
        float2 xv;
        {
            int b = tid >> 4, q = tid & 15;
            int c = q << 1, g = c >> 3, j = c & 7;
            xv = *(const float2*)&xz[((size_t)(b << 10) + tt) * NG + g * UN + u0 + j];
        }

        // 2) wait for all producers of h(step)
        if (tid < 64) {
            const unsigned tgt = base + 1 + step;
            unsigned v;
            do { v = ld_acq(&g_flag[d][tid]); } while ((int)(v - tgt) < 0);
        }
        __syncthreads();

        // 3) stage h (col-major A, [k][b]) and xz ([b][c])
        {
            const float4* src = (const float4*)&g_h[d][step & 1][0];
            float4* dst = (float4*)h_s;
#pragma unroll
            for (int i = 0; i < 8; ++i) dst[tid + i * 256] = __ldcg(src + tid + i * 256);
            int b = tid >> 4, c = (tid & 15) << 1;
            *(float2*)&xz_s[b * 32 + c] = xv;
        }
        __syncthreads();

        // 4) per-warp MMA: [16 x 32] partial over its 64-wide K chunk
        {
            wmma::fragment<wmma::accumulator, 16, 16, 8, float> acc0, acc1;
            wmma::fill_fragment(acc0, 0.0f);
            wmma::fill_fragment(acc1, 0.0f);
#pragma unroll
            for (int ks = 0; ks < 8; ++ks) {
                wmma::fragment<wmma::matrix_a, 16, 16, 8, wmma::precision::tf32,
                               wmma::col_major> af;
                wmma::load_matrix_sync(af, &h_s[(k0 + ks * 8) * 16], 16);
                wmma::mma_sync(acc0, af, bf[ks][0], acc0);
                wmma::mma_sync(acc1, af, bf[ks][1], acc1);
            }
            wmma::store_matrix_sync(&red[wid * 512], acc0, 32, wmma::mem_row_major);
            wmma::store_matrix_sync(&red[wid * 512 + 16], acc1, 32, wmma::mem_row_major);
        }
        __syncthreads();

        // 5) reduce 8 partials + xz -> zz ([b][c])
        {
            int b = tid >> 4, cp = (tid & 15) << 1;
            float2 v = *(const float2*)&xz_s[b * 32 + cp];
#pragma unroll
            for (int w = 0; w < 8; ++w) {
                float2 r = *(const float2*)&red[w * 512 + b * 32 + cp];
                v.x += r.x; v.y += r.y;
            }
            *(float2*)&zz_s[b * 32 + cp] = v;
        }
        __syncthreads();

        // 6) gates + state update + outputs
        if (tid < 128) {
            int ul = tid >> 4, b = tid & 15;
            float zi = zz_s[b * 32 + 0 * 8 + ul];
            float zf = zz_s[b * 32 + 1 * 8 + ul];
            float zg = zz_s[b * 32 + 2 * 8 + ul];
            float zo = zz_s[b * 32 + 3 * 8 + ul];
            float cc = sigm(zf) * c_s[tid] + sigm(zi) * sigm(zg);
            c_s[tid] = cc;
            float h = sigm(zo) * sigm(cc);
            g_h[d][(step & 1) ^ 1][(u0 + ul) * B_ + b] = tf32r(h);
            yout[((size_t)(b << 10) + tt) * (2 * UN) + (d << 9) + u0 + ul] = h;
        }
        __syncthreads();
        if (tid == 0) st_rel(&g_flag[d][cb], base + 2 + step);
    }
}

// ---------------- launcher ---------------------------------------------------
extern "C" void kernel_launch(void* const* d_in, const int* in_sizes, int n_in,
                              void* d_out, int out_size) {
    (void)in_sizes; (void)n_in; (void)out_size;
    const float* x  = (const float*)d_in[0];
    const float* W  = (const float*)d_in[1];
    const float* Uh = (const float*)d_in[2];
    const float* bb = (const float*)d_in[3];
    float* out = (float*)d_out;

    cudaFuncSetAttribute(lstm_gemm, cudaFuncAttributeMaxDynamicSharedMemorySize, GEMM_SMEM);
    cudaFuncSetAttribute(lstm_rec,  cudaFuncAttributeMaxDynamicSharedMemorySize, REC_SMEM);

    dim3 ggrid(NG / BN, M_ / BM, 2);
    for (int l = 0; l < NL; ++l) {
        int a_sel = (l == 0) ? 0 : 1 + ((l - 1) & 1);
        lstm_gemm<<<ggrid, 256, GEMM_SMEM>>>(x, a_sel,
                                             W + (size_t)l * 2 * DIN * NG,
                                             bb + (size_t)l * 2 * NG);
        int y_sel = (l == NL - 1) ? 2 : (l & 1);
        lstm_rec<<<128, 256, REC_SMEM>>>(Uh + (size_t)l * 2 * UN * NG, y_sel, out);
    }
}

// round 4
// speedup vs baseline: 1.5630x; 1.3713x over previous
#include <cuda_runtime.h>
#include <mma.h>

using namespace nvcuda;

typedef unsigned long long ull;

// Problem constants
#define B_   16
#define T_   1024
#define DIN  1024
#define UN   512
#define NG   2048          // 4*U
#define M_   (B_ * T_)     // 16384
#define NL   5

// ---------------- scratch (static __device__, allocation-free) -------------
__device__ float g_xz[2][(size_t)M_ * NG];     // per-dir input projections
__device__ float g_yb[2][(size_t)M_ * DIN];    // layer output ping-pong (+rounded x)
__device__ float g_wr[(size_t)NL * 2 * DIN * NG]; // tf32-rounded W
__device__ float g_h[2][2][UN * B_];           // h state ping-pong per dir [unit][b]

struct __align__(128) PFlag { unsigned v; };   // one flag per 128B L2 line
__device__ PFlag g_flag[2][64];

// ---------------- small helpers --------------------------------------------
__device__ __forceinline__ float sigm(float x) {
    return 1.0f / (1.0f + __expf(-x));
}
__device__ __forceinline__ float tf32r(float x) {
    unsigned u;
    asm("cvt.rna.tf32.f32 %0, %1;" : "=r"(u) : "f"(x));
    return __uint_as_float(u);
}
__device__ __forceinline__ void cp16(float* s, const float* g) {
    unsigned a = (unsigned)__cvta_generic_to_shared(s);
    asm volatile("cp.async.cg.shared.global [%0], [%1], 16;" :: "r"(a), "l"(g));
}
__device__ __forceinline__ void cp_commit() {
    asm volatile("cp.async.commit_group;" ::: "memory");
}
__device__ __forceinline__ void cp_wait0() {
    asm volatile("cp.async.wait_group 0;" ::: "memory");
}
__device__ __forceinline__ unsigned ld_acq(const unsigned* p) {
    unsigned v;
    asm volatile("ld.acquire.gpu.u32 %0, [%1];" : "=r"(v) : "l"(p) : "memory");
    return v;
}
__device__ __forceinline__ void st_rel(unsigned* p, unsigned v) {
    asm volatile("st.release.gpu.u32 [%0], %1;" :: "l"(p), "r"(v) : "memory");
}

// ---------------- tf32 pre-rounding (once per launch) -----------------------
__global__ void round_tf32(const float* __restrict__ in, float* __restrict__ out,
                           size_t n4) {
    size_t i = (size_t)blockIdx.x * blockDim.x + threadIdx.x;
    size_t stride = (size_t)gridDim.x * blockDim.x;
    for (; i < n4; i += stride) {
        float4 v = ((const float4*)in)[i];
        v.x = tf32r(v.x); v.y = tf32r(v.y); v.z = tf32r(v.z); v.w = tf32r(v.w);
        ((float4*)out)[i] = v;
    }
}

// ---------------- input-projection GEMM (TF32 wmma, cp.async pipelined) ----
// C[M_, NG] = A[M_, DIN] @ W[DIN, NG] + bias ; grid.z = direction
// A and W are pre-rounded canonical tf32 -> no in-loop conversions, no bias.
#define BM 128
#define BN 128
#define BK 32
#define AP 36
#define BP 136
#define ASZ (BM * AP)
#define BSZ (BK * BP)
#define GEMM_SMEM ((2 * ASZ + 2 * BSZ + 16 * BP) * 4)

__global__ void __launch_bounds__(256, 2) lstm_gemm(const float* __restrict__ A,
                                                    const float* __restrict__ Wl,
                                                    const float* __restrict__ bl) {
    extern __shared__ float gsm[];
    float* As = gsm;
    float* Bs = gsm + 2 * ASZ;
    float* Bias = gsm + 2 * ASZ + 2 * BSZ;

    const int d = blockIdx.z;
    const float* W = Wl + (size_t)d * DIN * NG;
    const float* bias = bl + d * NG;
    float* C = g_xz[d];

    const int tid = threadIdx.x;
    const int bn0 = blockIdx.x * BN;
    const int bm0 = blockIdx.y * BM;

    for (int i = tid; i < 16 * BN; i += 256) {
        int r = i >> 7, c = i & 127;
        Bias[r * BP + c] = bias[bn0 + c];
    }

    const int wid = tid >> 5;
    const int wr = wid >> 2;
    const int wc = wid & 3;

    const float* Abase = A + (size_t)bm0 * DIN;
    const float* Bbase = W + bn0;

    auto issue = [&](int kt, int buf) {
        float* Ad = As + buf * ASZ;
        const float* Ag = Abase + kt * BK;
#pragma unroll
        for (int i = 0; i < 4; ++i) {
            int id = tid + i * 256;
            int r = id >> 3, c4 = (id & 7) << 2;
            cp16(&Ad[r * AP + c4], &Ag[(size_t)r * DIN + c4]);
        }
        float* Bd = Bs + buf * BSZ;
        const float* Bg = Bbase + (size_t)kt * BK * NG;
#pragma unroll
        for (int i = 0; i < 4; ++i) {
            int id = tid + i * 256;
            int r = id >> 5, c4 = (id & 31) << 2;
            cp16(&Bd[r * BP + c4], &Bg[(size_t)r * NG + c4]);
        }
        cp_commit();
    };

    issue(0, 0);
    __syncthreads();

    wmma::fragment<wmma::accumulator, 16, 16, 8, float> acc[4][2];
#pragma unroll
    for (int mm = 0; mm < 4; ++mm)
#pragma unroll
        for (int nn = 0; nn < 2; ++nn)
            wmma::load_matrix_sync(acc[mm][nn], &Bias[wc * 32 + nn * 16], BP,
                                   wmma::mem_row_major);

    int buf = 0;
    const int NT = DIN / BK;
    for (int kt = 0; kt < NT; ++kt) {
        cp_wait0();
        __syncthreads();
        if (kt + 1 < NT) issue(kt + 1, buf ^ 1);

        float* Ab = As + buf * ASZ;
        float* Bb = Bs + buf * BSZ;
#pragma unroll
        for (int kk = 0; kk < 4; ++kk) {
            wmma::fragment<wmma::matrix_a, 16, 16, 8, wmma::precision::tf32,
                           wmma::row_major> af[4];
            wmma::fragment<wmma::matrix_b, 16, 16, 8, wmma::precision::tf32,
                           wmma::row_major> bf[2];
#pragma unroll
            for (int mm = 0; mm < 4; ++mm)
                wmma::load_matrix_sync(af[mm], &Ab[(wr * 64 + mm * 16) * AP + kk * 8], AP);
#pragma unroll
            for (int nn = 0; nn < 2; ++nn)
                wmma::load_matrix_sync(bf[nn], &Bb[kk * 8 * BP + wc * 32 + nn * 16], BP);
#pragma unroll
            for (int mm = 0; mm < 4; ++mm)
#pragma unroll
                for (int nn = 0; nn < 2; ++nn)
                    wmma::mma_sync(acc[mm][nn], af[mm], bf[nn], acc[mm][nn]);
        }
        __syncthreads();
        buf ^= 1;
    }

#pragma unroll
    for (int mm = 0; mm < 4; ++mm)
#pragma unroll
        for (int nn = 0; nn < 2; ++nn)
            wmma::store_matrix_sync(
                &C[(size_t)(bm0 + wr * 64 + mm * 16) * NG + bn0 + wc * 32 + nn * 16],
                acc[mm][nn], NG, wmma::mem_row_major);
}

// ---------------- persistent bidirectional recurrence (tensor-core) --------
// 128 CTAs: blocks 0..63 dir 0 (fwd), 64..127 dir 1 (rev).
// Each CTA owns 8 units -> 32 gate columns; Uh fragments register-resident.
// Per-warp dependency: warp wid needs only h[64*wid .. 64*wid+64) = flags of
// producer CTAs [8*wid, 8*wid+8). Flags are 128B-padded (no L2 line sharing).
#define OFF_UH   0                       // float[512*32]   65536 B (init only)
#define OFF_HS   65536                   // float[512*16]   32768 B  A col-major
#define OFF_RED  98304                   // float[8*512]    16384 B  warp partials
#define OFF_XZ   114688                  // float[16*32]     2048 B  [b][c]
#define OFF_ZZ   116736                  // float[16*32]     2048 B  [b][c]
#define OFF_CS   118784                  // float[128]        512 B
#define REC_SMEM 119296

__global__ void __launch_bounds__(256, 1) lstm_rec(const float* __restrict__ Uh_l,
                                                   int y_sel, float* __restrict__ out) {
    extern __shared__ char sm[];
    float* Uh_s = (float*)(sm + OFF_UH);
    float* h_s  = (float*)(sm + OFF_HS);
    float* red  = (float*)(sm + OFF_RED);
    float* xz_s = (float*)(sm + OFF_XZ);
    float* zz_s = (float*)(sm + OFF_ZZ);
    float* c_s  = (float*)(sm + OFF_CS);

    const int tid = threadIdx.x;
    const int d = blockIdx.x >> 6;
    const int cb = blockIdx.x & 63;
    const int u0 = cb * 8;
    const int wid = tid >> 5, lane = tid & 31;
    const int k0 = wid << 6;             // 64-wide K chunk per warp

    const float* Uh = Uh_l + (size_t)d * UN * NG;
    const float* xz = g_xz[d];
    float* yout = (y_sel == 0) ? g_yb[0] : (y_sel == 1 ? g_yb[1] : out);
    const bool final_layer = (y_sel == 2);

    const unsigned base = ld_acq(&g_flag[d][cb].v);

    // Uh slice -> smem (tf32-rounded): smem col c = g*8+j <-> global g*512+u0+j
    for (int i = tid; i < UN * 32; i += 256) {
        int k = i >> 5, c = i & 31;
        int g = c >> 3, j = c & 7;
        Uh_s[i] = tf32r(Uh[(size_t)k * NG + g * UN + u0 + j]);
    }
    if (tid < 128) {
        c_s[tid] = 0.0f;
        int ul = tid >> 4, b = tid & 15;
        g_h[d][0][(u0 + ul) * B_ + b] = 0.0f;   // zero initial h (own units)
    }
    __syncthreads();
    if (tid == 0) st_rel(&g_flag[d][cb].v, base + 1);   // zeros published

    // register-resident Uh fragments: 8 k-steps x 2 n-tiles per warp
    wmma::fragment<wmma::matrix_b, 16, 16, 8, wmma::precision::tf32,
                   wmma::row_major> bf[8][2];
#pragma unroll
    for (int ks = 0; ks < 8; ++ks)
#pragma unroll
        for (int nt = 0; nt < 2; ++nt)
            wmma::load_matrix_sync(bf[ks][nt], &Uh_s[(k0 + ks * 8) * 32 + nt * 16], 32);

    for (int step = 0; step < T_; ++step) {
        const int tt = d ? (T_ - 1 - step) : step;

        // 1) xz for this timestep -> xz_s[b][c]  (independent of flags)
        {
            int b = tid >> 4, q = tid & 15;
            int c = q << 1, g = c >> 3, j = c & 7;
            float2 xv = *(const float2*)&xz[((size_t)(b << 10) + tt) * NG + g * UN + u0 + j];
            *(float2*)&xz_s[b * 32 + c] = xv;
        }

        // 2) per-warp: wait only for this warp's 8 producer CTAs
        {
            const unsigned tgt = base + 1 + step;
            if (lane < 8) {
                const unsigned* fp = &g_flag[d][(wid << 3) + lane].v;
                unsigned v;
                do { v = ld_acq(fp); } while ((int)(v - tgt) < 0);
            }
            __syncwarp();
        }

        // 3) per-warp: stage own 64x16 h slice (L2-fresh)
        {
            const float4* src = (const float4*)(g_h[d][step & 1] + k0 * B_);
            float4* dst = (float4*)(h_s + k0 * B_);
#pragma unroll
            for (int i = 0; i < 8; ++i) dst[lane + i * 32] = __ldcg(src + lane + i * 32);
            __syncwarp();
        }

        // 4) per-warp MMA: [16 x 32] partial over its 64-wide K chunk
        {
            wmma::fragment<wmma::accumulator, 16, 16, 8, float> acc0, acc1;
            wmma::fill_fragment(acc0, 0.0f);
            wmma::fill_fragment(acc1, 0.0f);
#pragma unroll
            for (int ks = 0; ks < 8; ++ks) {
                wmma::fragment<wmma::matrix_a, 16, 16, 8, wmma::precision::tf32,
                               wmma::col_major> af;
                wmma::load_matrix_sync(af, &h_s[(k0 + ks * 8) * B_], B_);
                wmma::mma_sync(acc0, af, bf[ks][0], acc0);
                wmma::mma_sync(acc1, af, bf[ks][1], acc1);
            }
            wmma::store_matrix_sync(&red[wid * 512], acc0, 32, wmma::mem_row_major);
            wmma::store_matrix_sync(&red[wid * 512 + 16], acc1, 32, wmma::mem_row_major);
        }
        __syncthreads();

        // 5) reduce 8 partials + xz -> zz ([b][c])
        {
            int b = tid >> 4, cp = (tid & 15) << 1;
            float2 v = *(const float2*)&xz_s[b * 32 + cp];
#pragma unroll
            for (int w = 0; w < 8; ++w) {
                float2 r = *(const float2*)&red[w * 512 + b * 32 + cp];
                v.x += r.x; v.y += r.y;
            }
            *(float2*)&zz_s[b * 32 + cp] = v;
        }
        __syncthreads();

        // 6) gates + state update; release flag BEFORE the yout store
        float hv = 0.0f; size_t yidx = 0;
        if (tid < 128) {
            int ul = tid >> 4, b = tid & 15;
            float zi = zz_s[b * 32 + 0 * 8 + ul];
            float zf = zz_s[b * 32 + 1 * 8 + ul];
            float zg = zz_s[b * 32 + 2 * 8 + ul];
            float zo = zz_s[b * 32 + 3 * 8 + ul];
            float cc = sigm(zf) * c_s[tid] + sigm(zi) * sigm(zg);
            c_s[tid] = cc;
            float h = sigm(zo) * sigm(cc);
            float hr = tf32r(h);
            g_h[d][(step & 1) ^ 1][(u0 + ul) * B_ + b] = hr;
            hv = final_layer ? h : hr;  // intermediates pre-rounded for tf32 GEMM
            yidx = ((size_t)(b << 10) + tt) * (2 * UN) + (d << 9) + u0 + ul;
        }
        __syncthreads();
        if (tid == 0) st_rel(&g_flag[d][cb].v, base + 2 + step);
        if (tid < 128) yout[yidx] = hv;   // off critical path
    }
}

// ---------------- launcher ---------------------------------------------------
extern "C" void kernel_launch(void* const* d_in, const int* in_sizes, int n_in,
                              void* d_out, int out_size) {
    (void)in_sizes; (void)n_in; (void)out_size;
    const float* x  = (const float*)d_in[0];
    const float* W  = (const float*)d_in[1];
    const float* Uh = (const float*)d_in[2];
    const float* bb = (const float*)d_in[3];
    float* out = (float*)d_out;

    cudaFuncSetAttribute(lstm_gemm, cudaFuncAttributeMaxDynamicSharedMemorySize, GEMM_SMEM);
    cudaFuncSetAttribute(lstm_rec,  cudaFuncAttributeMaxDynamicSharedMemorySize, REC_SMEM);

    // pre-round x and W to canonical tf32 (removes all in-loop conversions)
    float* g_yb_p; cudaGetSymbolAddress((void**)&g_yb_p, g_yb);
    float* g_wr_p; cudaGetSymbolAddress((void**)&g_wr_p, g_wr);
    float* rx = g_yb_p + (size_t)M_ * DIN;   // g_yb[1]
    round_tf32<<<2048, 256>>>(x, rx, (size_t)M_ * DIN / 4);
    round_tf32<<<4096, 256>>>(W, g_wr_p, (size_t)NL * 2 * DIN * NG / 4);

    dim3 ggrid(NG / BN, M_ / BM, 2);
    for (int l = 0; l < NL; ++l) {
        const float* A = (l == 0) ? rx : (g_yb_p + (size_t)((l & 1) ^ 1) * M_ * DIN);
        lstm_gemm<<<ggrid, 256, GEMM_SMEM>>>(A,
                                             g_wr_p + (size_t)l * 2 * DIN * NG,
                                             bb + (size_t)l * 2 * NG);
        int y_sel = (l == NL - 1) ? 2 : (l & 1);
        lstm_rec<<<128, 256, REC_SMEM>>>(Uh + (size_t)l * 2 * UN * NG, y_sel, out);
    }
}

// round 5
// speedup vs baseline: 1.8252x; 1.1678x over previous
#include <cuda_runtime.h>
#include <mma.h>

using namespace nvcuda;

// Problem constants
#define B_   16
#define T_   1024
#define DIN  1024
#define UN   512
#define NG   2048          // 4*U
#define M_   (B_ * T_)     // 16384
#define NL   5

// ---------------- scratch (static __device__, allocation-free) -------------
__device__ float g_xz[2][(size_t)M_ * NG];     // per-dir input projections
__device__ float g_yb[2][(size_t)M_ * DIN];    // layer output ping-pong (+rounded x)
__device__ float g_wr[(size_t)NL * 2 * DIN * NG]; // tf32-rounded W
__device__ float g_h[2][2][UN * B_];           // tagged h, [dir][buf][unit*16+b]

// ---------------- small helpers --------------------------------------------
__device__ __forceinline__ float sigm(float x) {
    return 1.0f / (1.0f + __expf(-x));
}
__device__ __forceinline__ float tf32r(float x) {
    unsigned u;
    asm("cvt.rna.tf32.f32 %0, %1;" : "=r"(u) : "f"(x));
    return __uint_as_float(u);
}
__device__ __forceinline__ void cp16(float* s, const float* g) {
    unsigned a = (unsigned)__cvta_generic_to_shared(s);
    asm volatile("cp.async.cg.shared.global [%0], [%1], 16;" :: "r"(a), "l"(g));
}
__device__ __forceinline__ void cp_commit() {
    asm volatile("cp.async.commit_group;" ::: "memory");
}
__device__ __forceinline__ void cp_wait0() {
    asm volatile("cp.async.wait_group 0;" ::: "memory");
}
__device__ __forceinline__ float4 ldv4_vol(const float4* p) {
    float4 v;
    asm volatile("ld.volatile.global.v4.f32 {%0,%1,%2,%3}, [%4];"
                 : "=f"(v.x), "=f"(v.y), "=f"(v.z), "=f"(v.w) : "l"(p) : "memory");
    return v;
}
__device__ __forceinline__ void st_vol(float* p, float v) {
    asm volatile("st.volatile.global.f32 [%0], %1;" :: "l"(p), "f"(v) : "memory");
}

// ---------------- tf32 pre-rounding (once per launch) -----------------------
__global__ void round_tf32(const float* __restrict__ in, float* __restrict__ out,
                           size_t n4) {
    size_t i = (size_t)blockIdx.x * blockDim.x + threadIdx.x;
    size_t stride = (size_t)gridDim.x * blockDim.x;
    for (; i < n4; i += stride) {
        float4 v = ((const float4*)in)[i];
        v.x = tf32r(v.x); v.y = tf32r(v.y); v.z = tf32r(v.z); v.w = tf32r(v.w);
        ((float4*)out)[i] = v;
    }
}

// ---------------- input-projection GEMM (TF32 wmma, cp.async pipelined) ----
#define BM 128
#define BN 128
#define BK 32
#define AP 36
#define BP 136
#define ASZ (BM * AP)
#define BSZ (BK * BP)
#define GEMM_SMEM ((2 * ASZ + 2 * BSZ + 16 * BP) * 4)

__global__ void __launch_bounds__(256, 2) lstm_gemm(const float* __restrict__ A,
                                                    const float* __restrict__ Wl,
                                                    const float* __restrict__ bl) {
    extern __shared__ float gsm[];
    float* As = gsm;
    float* Bs = gsm + 2 * ASZ;
    float* Bias = gsm + 2 * ASZ + 2 * BSZ;

    const int d = blockIdx.z;
    const float* W = Wl + (size_t)d * DIN * NG;
    const float* bias = bl + d * NG;
    float* C = g_xz[d];

    const int tid = threadIdx.x;
    const int bn0 = blockIdx.x * BN;
    const int bm0 = blockIdx.y * BM;

    for (int i = tid; i < 16 * BN; i += 256) {
        int r = i >> 7, c = i & 127;
        Bias[r * BP + c] = bias[bn0 + c];
    }

    const int wid = tid >> 5;
    const int wr = wid >> 2;
    const int wc = wid & 3;

    const float* Abase = A + (size_t)bm0 * DIN;
    const float* Bbase = W + bn0;

    auto issue = [&](int kt, int buf) {
        float* Ad = As + buf * ASZ;
        const float* Ag = Abase + kt * BK;
#pragma unroll
        for (int i = 0; i < 4; ++i) {
            int id = tid + i * 256;
            int r = id >> 3, c4 = (id & 7) << 2;
            cp16(&Ad[r * AP + c4], &Ag[(size_t)r * DIN + c4]);
        }
        float* Bd = Bs + buf * BSZ;
        const float* Bg = Bbase + (size_t)kt * BK * NG;
#pragma unroll
        for (int i = 0; i < 4; ++i) {
            int id = tid + i * 256;
            int r = id >> 5, c4 = (id & 31) << 2;
            cp16(&Bd[r * BP + c4], &Bg[(size_t)r * NG + c4]);
        }
        cp_commit();
    };

    issue(0, 0);
    __syncthreads();

    wmma::fragment<wmma::accumulator, 16, 16, 8, float> acc[4][2];
#pragma unroll
    for (int mm = 0; mm < 4; ++mm)
#pragma unroll
        for (int nn = 0; nn < 2; ++nn)
            wmma::load_matrix_sync(acc[mm][nn], &Bias[wc * 32 + nn * 16], BP,
                                   wmma::mem_row_major);

    int buf = 0;
    const int NT = DIN / BK;
    for (int kt = 0; kt < NT; ++kt) {
        cp_wait0();
        __syncthreads();
        if (kt + 1 < NT) issue(kt + 1, buf ^ 1);

        float* Ab = As + buf * ASZ;
        float* Bb = Bs + buf * BSZ;
#pragma unroll
        for (int kk = 0; kk < 4; ++kk) {
            wmma::fragment<wmma::matrix_a, 16, 16, 8, wmma::precision::tf32,
                           wmma::row_major> af[4];
            wmma::fragment<wmma::matrix_b, 16, 16, 8, wmma::precision::tf32,
                           wmma::row_major> bf[2];
#pragma unroll
            for (int mm = 0; mm < 4; ++mm)
                wmma::load_matrix_sync(af[mm], &Ab[(wr * 64 + mm * 16) * AP + kk * 8], AP);
#pragma unroll
            for (int nn = 0; nn < 2; ++nn)
                wmma::load_matrix_sync(bf[nn], &Bb[kk * 8 * BP + wc * 32 + nn * 16], BP);
#pragma unroll
            for (int mm = 0; mm < 4; ++mm)
#pragma unroll
                for (int nn = 0; nn < 2; ++nn)
                    wmma::mma_sync(acc[mm][nn], af[mm], bf[nn], acc[mm][nn]);
        }
        __syncthreads();
        buf ^= 1;
    }

#pragma unroll
    for (int mm = 0; mm < 4; ++mm)
#pragma unroll
        for (int nn = 0; nn < 2; ++nn)
            wmma::store_matrix_sync(
                &C[(size_t)(bm0 + wr * 64 + mm * 16) * NG + bn0 + wc * 32 + nn * 16],
                acc[mm][nn], NG, wmma::mem_row_major);
}

// ---------------- persistent bidirectional recurrence (tensor-core) --------
// 128 CTAs: blocks 0..63 dir 0 (fwd), 64..127 dir 1 (rev). CTA owns 8 units.
// Flagless sync: h values carry a phase tag (offset 2.0 or 4.0). One L2 round
// trip per handoff; per-word atomicity makes the load self-synchronizing.
// Tag schedule: hin_s lives in buf[s&1] with offset 2+2*((s>>1)&1). Final-step
// store skipped so stale tags always mismatch across launches/replays.
#define OFF_HS   0                       // float[512*16]   32768 B (per-warp private)
#define OFF_RED  32768                   // float[8*512]    16384 B
#define OFF_XZ   49152                   // float[16*32]     2048 B
#define OFF_ZZ   51200                   // float[16*32]     2048 B
#define OFF_CS   53248                   // float[128]        512 B
#define REC_SMEM 65536                   // Uh staging aliases [0,64K) during init

__global__ void __launch_bounds__(256, 1) lstm_rec(const float* __restrict__ Uh_l,
                                                   int y_sel, float* __restrict__ out) {
    extern __shared__ char sm[];
    float* Uh_s = (float*)(sm);          // init-only staging, aliases everything
    float* h_s  = (float*)(sm + OFF_HS);
    float* red  = (float*)(sm + OFF_RED);
    float* xz_s = (float*)(sm + OFF_XZ);
    float* zz_s = (float*)(sm + OFF_ZZ);
    float* c_s  = (float*)(sm + OFF_CS);

    const int tid = threadIdx.x;
    const int d = blockIdx.x >> 6;
    const int cb = blockIdx.x & 63;
    const int u0 = cb * 8;
    const int wid = tid >> 5, lane = tid & 31;
    const int k0 = wid << 6;             // 64-wide K chunk per warp

    const float* Uh = Uh_l + (size_t)d * UN * NG;
    const float* xz = g_xz[d];
    float* yout = (y_sel == 0) ? g_yb[0] : (y_sel == 1 ? g_yb[1] : out);
    const bool final_layer = (y_sel == 2);

    // ---- init: stage Uh (tf32) and load register fragments ----
    for (int i = tid; i < UN * 32; i += 256) {
        int k = i >> 5, c = i & 31;
        int g = c >> 3, j = c & 7;
        Uh_s[i] = tf32r(Uh[(size_t)k * NG + g * UN + u0 + j]);
    }
    __syncthreads();

    wmma::fragment<wmma::matrix_b, 16, 16, 8, wmma::precision::tf32,
                   wmma::row_major> bf[8][2];
#pragma unroll
    for (int ks = 0; ks < 8; ++ks)
#pragma unroll
        for (int nt = 0; nt < 2; ++nt)
            wmma::load_matrix_sync(bf[ks][nt], &Uh_s[(k0 + ks * 8) * 32 + nt * 16], 32);
    __syncthreads();

    // publish hin_0 = zeros (tag offset 2.0); c = 0
    if (tid < 128) {
        c_s[tid] = 0.0f;
        int ul = tid >> 4, b = tid & 15;
        st_vol(&g_h[d][0][(u0 + ul) * B_ + b], 2.0f);
    }
    __syncthreads();

    for (int step = 0; step < T_; ++step) {
        const int tt = d ? (T_ - 1 - step) : step;
        const float e  = 2.0f + 2.0f * (float)((step >> 1) & 1);  // expected offset
        const float e1 = e + 1.0f;

        // 1) xz for this timestep -> regs (overlaps the spin below)
        float2 xv;
        {
            int b = tid >> 4, q = tid & 15;
            int c = q << 1, g = c >> 3, j = c & 7;
            xv = *(const float2*)&xz[((size_t)(b << 10) + tt) * NG + g * UN + u0 + j];
        }

        // 2) per-warp: spin-load own 64x16 h slice (self-tagged, single L2 RT)
        {
            const float4* src = (const float4*)(g_h[d][step & 1]) + k0 * 4;
            float4 v[8];
            unsigned done = 0;
            while (done != 0xFFu) {
#pragma unroll
                for (int i = 0; i < 8; ++i)
                    if (!((done >> i) & 1)) v[i] = ldv4_vol(src + lane + i * 32);
#pragma unroll
                for (int i = 0; i < 8; ++i)
                    if (!((done >> i) & 1)) {
                        bool ok = (v[i].x >= e) & (v[i].x < e1) &
                                  (v[i].y >= e) & (v[i].y < e1) &
                                  (v[i].z >= e) & (v[i].z < e1) &
                                  (v[i].w >= e) & (v[i].w < e1);
                        if (ok) done |= 1u << i;
                    }
            }
            float4* dst = (float4*)(h_s + k0 * B_);
#pragma unroll
            for (int i = 0; i < 8; ++i) {
                float4 hd = make_float4(v[i].x - e, v[i].y - e, v[i].z - e, v[i].w - e);
                dst[lane + i * 32] = hd;
            }
            __syncwarp();
        }

        // 3) per-warp MMA: [16 x 32] partial over its 64-wide K chunk
        {
            wmma::fragment<wmma::accumulator, 16, 16, 8, float> acc0, acc1;
            wmma::fill_fragment(acc0, 0.0f);
            wmma::fill_fragment(acc1, 0.0f);
#pragma unroll
            for (int ks = 0; ks < 8; ++ks) {
                wmma::fragment<wmma::matrix_a, 16, 16, 8, wmma::precision::tf32,
                               wmma::col_major> af;
                wmma::load_matrix_sync(af, &h_s[(k0 + ks * 8) * B_], B_);
                wmma::mma_sync(acc0, af, bf[ks][0], acc0);
                wmma::mma_sync(acc1, af, bf[ks][1], acc1);
            }
            wmma::store_matrix_sync(&red[wid * 512], acc0, 32, wmma::mem_row_major);
            wmma::store_matrix_sync(&red[wid * 512 + 16], acc1, 32, wmma::mem_row_major);
        }
        // xz -> smem (needed by reduce phase)
        {
            int b = tid >> 4, c = (tid & 15) << 1;
            *(float2*)&xz_s[b * 32 + c] = xv;
        }
        __syncthreads();

        // 4) reduce 8 partials + xz -> zz ([b][c])
        {
            int b = tid >> 4, cp = (tid & 15) << 1;
            float2 v = *(const float2*)&xz_s[b * 32 + cp];
#pragma unroll
            for (int w = 0; w < 8; ++w) {
                float2 r = *(const float2*)&red[w * 512 + b * 32 + cp];
                v.x += r.x; v.y += r.y;
            }
            *(float2*)&zz_s[b * 32 + cp] = v;
        }
        __syncthreads();

        // 5) gates + state update; publish tagged h IMMEDIATELY (no barrier)
        if (tid < 128) {
            int ul = tid >> 4, b = tid & 15;
            float zi = zz_s[b * 32 + 0 * 8 + ul];
            float zf = zz_s[b * 32 + 1 * 8 + ul];
            float zg = zz_s[b * 32 + 2 * 8 + ul];
            float zo = zz_s[b * 32 + 3 * 8 + ul];
            float cc = sigm(zf) * c_s[tid] + sigm(zi) * sigm(zg);
            c_s[tid] = cc;
            float h = sigm(zo) * sigm(cc);
            float hr = tf32r(h);
            if (step < T_ - 1) {
                float off = 2.0f + 2.0f * (float)(((step + 1) >> 1) & 1);
                st_vol(&g_h[d][(step + 1) & 1][(u0 + ul) * B_ + b], hr + off);
            }
            float hv = final_layer ? h : hr;
            yout[((size_t)(b << 10) + tt) * (2 * UN) + (d << 9) + u0 + ul] = hv;
        }
        // no trailing barrier: h_s is warp-private; xz_s/red/zz_s protected by
        // the two syncthreads above on the next iteration's path
    }
}

// ---------------- launcher ---------------------------------------------------
extern "C" void kernel_launch(void* const* d_in, const int* in_sizes, int n_in,
                              void* d_out, int out_size) {
    (void)in_sizes; (void)n_in; (void)out_size;
    const float* x  = (const float*)d_in[0];
    const float* W  = (const float*)d_in[1];
    const float* Uh = (const float*)d_in[2];
    const float* bb = (const float*)d_in[3];
    float* out = (float*)d_out;

    cudaFuncSetAttribute(lstm_gemm, cudaFuncAttributeMaxDynamicSharedMemorySize, GEMM_SMEM);
    cudaFuncSetAttribute(lstm_rec,  cudaFuncAttributeMaxDynamicSharedMemorySize, REC_SMEM);

    float* g_yb_p; cudaGetSymbolAddress((void**)&g_yb_p, g_yb);
    float* g_wr_p; cudaGetSymbolAddress((void**)&g_wr_p, g_wr);
    float* rx = g_yb_p + (size_t)M_ * DIN;   // g_yb[1]
    round_tf32<<<2048, 256>>>(x, rx, (size_t)M_ * DIN / 4);
    round_tf32<<<4096, 256>>>(W, g_wr_p, (size_t)NL * 2 * DIN * NG / 4);

    dim3 ggrid(NG / BN, M_ / BM, 2);
    for (int l = 0; l < NL; ++l) {
        const float* A = (l == 0) ? rx : (g_yb_p + (size_t)((l & 1) ^ 1) * M_ * DIN);
        lstm_gemm<<<ggrid, 256, GEMM_SMEM>>>(A,
                                             g_wr_p + (size_t)l * 2 * DIN * NG,
                                             bb + (size_t)l * 2 * NG);
        int y_sel = (l == NL - 1) ? 2 : (l & 1);
        lstm_rec<<<128, 256, REC_SMEM>>>(Uh + (size_t)l * 2 * UN * NG, y_sel, out);
    }
}

// round 6
// speedup vs baseline: 1.8646x; 1.0216x over previous
#include <cuda_runtime.h>
#include <mma.h>

using namespace nvcuda;

// Problem constants
#define B_   16
#define T_   1024
#define DIN  1024
#define UN   512
#define NG   2048          // 4*U
#define M_   (B_ * T_)     // 16384
#define NL   5
#define NREG 8             // h replication regions (contention relief)

// ---------------- scratch (static __device__, allocation-free) -------------
__device__ float g_xz[2][(size_t)M_ * NG];     // per-dir input projections
__device__ float g_yb[2][(size_t)M_ * DIN];    // layer output ping-pong (+rounded x)
__device__ float g_wr[(size_t)NL * 2 * DIN * NG]; // tf32-rounded W
__device__ float g_h2[2][2][NREG][UN * B_];    // tagged h, replicated x8

// ---------------- small helpers --------------------------------------------
__device__ __forceinline__ float sigm(float x) {
    return 1.0f / (1.0f + __expf(-x));
}
__device__ __forceinline__ float tf32r(float x) {
    unsigned u;
    asm("cvt.rna.tf32.f32 %0, %1;" : "=r"(u) : "f"(x));
    return __uint_as_float(u);
}
__device__ __forceinline__ void cp16(float* s, const float* g) {
    unsigned a = (unsigned)__cvta_generic_to_shared(s);
    asm volatile("cp.async.cg.shared.global [%0], [%1], 16;" :: "r"(a), "l"(g));
}
__device__ __forceinline__ void cp_commit() {
    asm volatile("cp.async.commit_group;" ::: "memory");
}
__device__ __forceinline__ void cp_wait0() {
    asm volatile("cp.async.wait_group 0;" ::: "memory");
}
__device__ __forceinline__ float4 ldv4_vol(const float4* p) {
    float4 v;
    asm volatile("ld.volatile.global.v4.f32 {%0,%1,%2,%3}, [%4];"
                 : "=f"(v.x), "=f"(v.y), "=f"(v.z), "=f"(v.w) : "l"(p) : "memory");
    return v;
}
__device__ __forceinline__ void st_vol(float* p, float v) {
    asm volatile("st.volatile.global.f32 [%0], %1;" :: "l"(p), "f"(v) : "memory");
}

// ---------------- tf32 pre-rounding (once per launch) -----------------------
__global__ void round_tf32(const float* __restrict__ in, float* __restrict__ out,
                           size_t n4) {
    size_t i = (size_t)blockIdx.x * blockDim.x + threadIdx.x;
    size_t stride = (size_t)gridDim.x * blockDim.x;
    for (; i < n4; i += stride) {
        float4 v = ((const float4*)in)[i];
        v.x = tf32r(v.x); v.y = tf32r(v.y); v.z = tf32r(v.z); v.w = tf32r(v.w);
        ((float4*)out)[i] = v;
    }
}

// ---------------- input-projection GEMM (TF32 wmma, cp.async, 64x64 warp) --
#define BM 128
#define BN 128
#define BK 32
#define AP 36
#define BP 136
#define ASZ (BM * AP)
#define BSZ (BK * BP)
#define GEMM_SMEM ((2 * ASZ + 2 * BSZ + 16 * BP) * 4)

__global__ void __launch_bounds__(128, 2) lstm_gemm(const float* __restrict__ A,
                                                    const float* __restrict__ Wl,
                                                    const float* __restrict__ bl) {
    extern __shared__ float gsm[];
    float* As = gsm;
    float* Bs = gsm + 2 * ASZ;
    float* Bias = gsm + 2 * ASZ + 2 * BSZ;

    const int d = blockIdx.z;
    const float* W = Wl + (size_t)d * DIN * NG;
    const float* bias = bl + d * NG;
    float* C = g_xz[d];

    const int tid = threadIdx.x;
    const int bn0 = blockIdx.x * BN;
    const int bm0 = blockIdx.y * BM;

    for (int i = tid; i < 16 * BN; i += 128) {
        int r = i >> 7, c = i & 127;
        Bias[r * BP + c] = bias[bn0 + c];
    }

    const int wid = tid >> 5;
    const int wr = wid >> 1;   // 0..1 -> 64-row slab
    const int wc = wid & 1;    // 0..1 -> 64-col slab

    const float* Abase = A + (size_t)bm0 * DIN;
    const float* Bbase = W + bn0;

    auto issue = [&](int kt, int buf) {
        float* Ad = As + buf * ASZ;
        const float* Ag = Abase + kt * BK;
#pragma unroll
        for (int i = 0; i < 8; ++i) {
            int id = tid + i * 128;
            int r = id >> 3, c4 = (id & 7) << 2;
            cp16(&Ad[r * AP + c4], &Ag[(size_t)r * DIN + c4]);
        }
        float* Bd = Bs + buf * BSZ;
        const float* Bg = Bbase + (size_t)kt * BK * NG;
#pragma unroll
        for (int i = 0; i < 8; ++i) {
            int id = tid + i * 128;
            int r = id >> 5, c4 = (id & 31) << 2;
            cp16(&Bd[r * BP + c4], &Bg[(size_t)r * NG + c4]);
        }
        cp_commit();
    };

    issue(0, 0);
    __syncthreads();

    wmma::fragment<wmma::accumulator, 16, 16, 8, float> acc[4][4];
#pragma unroll
    for (int mm = 0; mm < 4; ++mm)
#pragma unroll
        for (int nn = 0; nn < 4; ++nn)
            wmma::load_matrix_sync(acc[mm][nn], &Bias[wc * 64 + nn * 16], BP,
                                   wmma::mem_row_major);

    int buf = 0;
    const int NT = DIN / BK;
    for (int kt = 0; kt < NT; ++kt) {
        cp_wait0();
        __syncthreads();
        if (kt + 1 < NT) issue(kt + 1, buf ^ 1);

        float* Ab = As + buf * ASZ;
        float* Bb = Bs + buf * BSZ;
#pragma unroll
        for (int kk = 0; kk < 4; ++kk) {
            wmma::fragment<wmma::matrix_a, 16, 16, 8, wmma::precision::tf32,
                           wmma::row_major> af[4];
            wmma::fragment<wmma::matrix_b, 16, 16, 8, wmma::precision::tf32,
                           wmma::row_major> bf[4];
#pragma unroll
            for (int mm = 0; mm < 4; ++mm)
                wmma::load_matrix_sync(af[mm], &Ab[(wr * 64 + mm * 16) * AP + kk * 8], AP);
#pragma unroll
            for (int nn = 0; nn < 4; ++nn)
                wmma::load_matrix_sync(bf[nn], &Bb[kk * 8 * BP + wc * 64 + nn * 16], BP);
#pragma unroll
            for (int mm = 0; mm < 4; ++mm)
#pragma unroll
                for (int nn = 0; nn < 4; ++nn)
                    wmma::mma_sync(acc[mm][nn], af[mm], bf[nn], acc[mm][nn]);
        }
        __syncthreads();
        buf ^= 1;
    }

#pragma unroll
    for (int mm = 0; mm < 4; ++mm)
#pragma unroll
        for (int nn = 0; nn < 4; ++nn)
            wmma::store_matrix_sync(
                &C[(size_t)(bm0 + wr * 64 + mm * 16) * NG + bn0 + wc * 64 + nn * 16],
                acc[mm][nn], NG, wmma::mem_row_major);
}

// ---------------- persistent bidirectional recurrence (tensor-core) --------
// 128 CTAs: blocks 0..63 dir 0 (fwd), 64..127 dir 1 (rev). CTA owns 8 units.
// Flagless tagged-h sync, replicated into 8 regions (octant cb>>3 polls its
// own copy -> 64 pollers per line instead of 512). One __syncthreads/step:
// red/xz double-buffered by step parity; reduce fused into gate threads.
#define OFF_HS   0                       // float[512*16]        32768 B
#define OFF_RED  32768                   // float[2][8][512]     32768 B (col-major ldm16)
#define OFF_XZ   65536                   // float[2][16*36]       4608 B
#define OFF_CS   70144                   // float[128]             512 B
#define REC_SMEM 70656                   // Uh staging aliases [0,64K) at init

__global__ void __launch_bounds__(256, 1) lstm_rec(const float* __restrict__ Uh_l,
                                                   int y_sel, float* __restrict__ out) {
    extern __shared__ char sm[];
    float* Uh_s = (float*)(sm);          // init-only staging (aliases h_s+red)
    float* h_s  = (float*)(sm + OFF_HS);
    float* red  = (float*)(sm + OFF_RED);
    float* xz_s = (float*)(sm + OFF_XZ);
    float* c_s  = (float*)(sm + OFF_CS);

    const int tid = threadIdx.x;
    const int d = blockIdx.x >> 6;
    const int cb = blockIdx.x & 63;
    const int u0 = cb * 8;
    const int reg = cb >> 3;             // consumer octant -> region
    const int wid = tid >> 5, lane = tid & 31;
    const int k0 = wid << 6;             // 64-wide K chunk per warp

    const float* Uh = Uh_l + (size_t)d * UN * NG;
    const float* xz = g_xz[d];
    float* yout = (y_sel == 0) ? g_yb[0] : (y_sel == 1 ? g_yb[1] : out);
    const bool final_layer = (y_sel == 2);

    // ---- init: stage Uh (tf32) and load register fragments ----
    for (int i = tid; i < UN * 32; i += 256) {
        int k = i >> 5, c = i & 31;
        int g = c >> 3, j = c & 7;
        Uh_s[i] = tf32r(Uh[(size_t)k * NG + g * UN + u0 + j]);
    }
    __syncthreads();

    wmma::fragment<wmma::matrix_b, 16, 16, 8, wmma::precision::tf32,
                   wmma::row_major> bfr[8][2];
#pragma unroll
    for (int ks = 0; ks < 8; ++ks)
#pragma unroll
        for (int nt = 0; nt < 2; ++nt)
            wmma::load_matrix_sync(bfr[ks][nt], &Uh_s[(k0 + ks * 8) * 32 + nt * 16], 32);
    __syncthreads();

    // publish hin_0 = zeros (tag 2.0) into all 8 regions; c = 0
    if (tid < 128) {
        c_s[tid] = 0.0f;
        int ul = tid >> 4, b = tid & 15;
        float* base = &g_h2[d][0][0][(u0 + ul) * B_ + b];
#pragma unroll
        for (int r = 0; r < NREG; ++r) st_vol(base + r * (UN * B_), 2.0f);
    }
    __syncthreads();

    for (int step = 0; step < T_; ++step) {
        const int tt = d ? (T_ - 1 - step) : step;
        const int p = step & 1;
        const float e  = 2.0f + 2.0f * (float)((step >> 1) & 1);
        const float e1 = e + 1.0f;       // inclusive: tf32r(h) can be exactly 1

        // 1) xz for this timestep -> regs
        float2 xv;
        {
            int b = tid >> 4, q = tid & 15;
            int c = q << 1, g = c >> 3, j = c & 7;
            xv = *(const float2*)&xz[((size_t)(b << 10) + tt) * NG + g * UN + u0 + j];
        }

        // 2) per-warp: spin-load own 64x16 h slice from own region
        {
            const float4* src = (const float4*)(g_h2[d][p][reg]) + k0 * 4;
            float4 v[8];
            unsigned done = 0;
            while (done != 0xFFu) {
#pragma unroll
                for (int i = 0; i < 8; ++i)
                    if (!((done >> i) & 1)) v[i] = ldv4_vol(src + lane + i * 32);
#pragma unroll
                for (int i = 0; i < 8; ++i)
                    if (!((done >> i) & 1)) {
                        bool ok = (v[i].x >= e) & (v[i].x <= e1) &
                                  (v[i].y >= e) & (v[i].y <= e1) &
                                  (v[i].z >= e) & (v[i].z <= e1) &
                                  (v[i].w >= e) & (v[i].w <= e1);
                        if (ok) done |= 1u << i;
                    }
            }
            float4* dst = (float4*)(h_s + k0 * B_);
#pragma unroll
            for (int i = 0; i < 8; ++i)
                dst[lane + i * 32] = make_float4(v[i].x - e, v[i].y - e,
                                                 v[i].z - e, v[i].w - e);
            __syncwarp();
        }

        // 3) xz -> smem buffer p
        {
            int b = tid >> 4, c = (tid & 15) << 1;
            *(float2*)&xz_s[p * 576 + b * 36 + c] = xv;
        }

        // 4) per-warp MMA, split accumulator chains; store col-major (ldm 16)
        {
            wmma::fragment<wmma::accumulator, 16, 16, 8, float> a0a, a0b, a1a, a1b;
            wmma::fill_fragment(a0a, 0.0f); wmma::fill_fragment(a0b, 0.0f);
            wmma::fill_fragment(a1a, 0.0f); wmma::fill_fragment(a1b, 0.0f);
#pragma unroll
            for (int ks = 0; ks < 8; ks += 2) {
                wmma::fragment<wmma::matrix_a, 16, 16, 8, wmma::precision::tf32,
                               wmma::col_major> af0, af1;
                wmma::load_matrix_sync(af0, &h_s[(k0 + ks * 8) * B_], B_);
                wmma::load_matrix_sync(af1, &h_s[(k0 + (ks + 1) * 8) * B_], B_);
                wmma::mma_sync(a0a, af0, bfr[ks][0], a0a);
                wmma::mma_sync(a1a, af0, bfr[ks][1], a1a);
                wmma::mma_sync(a0b, af1, bfr[ks + 1][0], a0b);
                wmma::mma_sync(a1b, af1, bfr[ks + 1][1], a1b);
            }
#pragma unroll
            for (int i = 0; i < a0a.num_elements; ++i) {
                a0a.x[i] += a0b.x[i];
                a1a.x[i] += a1b.x[i];
            }
            float* rb = &red[(p * 8 + wid) * 512];
            wmma::store_matrix_sync(rb, a0a, 16, wmma::mem_col_major);
            wmma::store_matrix_sync(rb + 256, a1a, 16, wmma::mem_col_major);
        }
        __syncthreads();   // the ONLY barrier per step

        // 5) fused reduce + gates + publish (warps 0-3)
        if (tid < 128) {
            int ul = tid >> 4, b = tid & 15;
            float v0 = xz_s[p * 576 + b * 36 + 0 * 8 + ul];
            float v1 = xz_s[p * 576 + b * 36 + 1 * 8 + ul];
            float v2 = xz_s[p * 576 + b * 36 + 2 * 8 + ul];
            float v3 = xz_s[p * 576 + b * 36 + 3 * 8 + ul];
#pragma unroll
            for (int w = 0; w < 8; ++w) {
                const float* rb = &red[(p * 8 + w) * 512];
                v0 += rb[(0 * 8 + ul) * 16 + b];
                v1 += rb[(1 * 8 + ul) * 16 + b];
                v2 += rb[(2 * 8 + ul) * 16 + b];
                v3 += rb[(3 * 8 + ul) * 16 + b];
            }
            float cc = sigm(v1) * c_s[tid] + sigm(v0) * sigm(v2);
            c_s[tid] = cc;
            float h = sigm(v3) * sigm(cc);
            float hr = tf32r(h);
            if (step < T_ - 1) {
                float tv = hr + 2.0f + 2.0f * (float)(((step + 1) >> 1) & 1);
                float* base = &g_h2[d][(step + 1) & 1][0][(u0 + ul) * B_ + b];
#pragma unroll
                for (int r = 0; r < NREG; ++r) st_vol(base + r * (UN * B_), tv);
            }
            float hv = final_layer ? h : hr;
            yout[((size_t)(b << 10) + tt) * (2 * UN) + (d << 9) + u0 + ul] = hv;
        }
        // no trailing barrier: red/xz double-buffered; h_s warp-private;
        // step+2 reuse of buffer p gated by the sync above.
    }
}

// ---------------- launcher ---------------------------------------------------
extern "C" void kernel_launch(void* const* d_in, const int* in_sizes, int n_in,
                              void* d_out, int out_size) {
    (void)in_sizes; (void)n_in; (void)out_size;
    const float* x  = (const float*)d_in[0];
    const float* W  = (const float*)d_in[1];
    const float* Uh = (const float*)d_in[2];
    const float* bb = (const float*)d_in[3];
    float* out = (float*)d_out;

    cudaFuncSetAttribute(lstm_gemm, cudaFuncAttributeMaxDynamicSharedMemorySize, GEMM_SMEM);
    cudaFuncSetAttribute(lstm_rec,  cudaFuncAttributeMaxDynamicSharedMemorySize, REC_SMEM);

    float* g_yb_p; cudaGetSymbolAddress((void**)&g_yb_p, g_yb);
    float* g_wr_p; cudaGetSymbolAddress((void**)&g_wr_p, g_wr);
    float* rx = g_yb_p + (size_t)M_ * DIN;   // g_yb[1]
    round_tf32<<<2048, 256>>>(x, rx, (size_t)M_ * DIN / 4);
    round_tf32<<<4096, 256>>>(W, g_wr_p, (size_t)NL * 2 * DIN * NG / 4);

    dim3 ggrid(NG / BN, M_ / BM, 2);
    for (int l = 0; l < NL; ++l) {
        const float* A = (l == 0) ? rx : (g_yb_p + (size_t)((l & 1) ^ 1) * M_ * DIN);
        lstm_gemm<<<ggrid, 128, GEMM_SMEM>>>(A,
                                             g_wr_p + (size_t)l * 2 * DIN * NG,
                                             bb + (size_t)l * 2 * NG);
        int y_sel = (l == NL - 1) ? 2 : (l & 1);
        lstm_rec<<<128, 256, REC_SMEM>>>(Uh + (size_t)l * 2 * UN * NG, y_sel, out);
    }
}

// round 7
// speedup vs baseline: 2.9677x; 1.5916x over previous
#include <cuda_runtime.h>
#include <cuda_fp16.h>
#include <mma.h>

using namespace nvcuda;

// Problem constants
#define B_   16
#define T_   1024
#define DIN  1024
#define UN   512
#define NG   2048          // 4*U
#define M_   (B_ * T_)     // 16384
#define NL   5
#define NREG 8             // h replication regions

// ---------------- scratch (static __device__, allocation-free) -------------
__device__ float g_xz[2][(size_t)M_ * NG];             // per-dir input projections (fp32)
__device__ __align__(16) __half g_yh[2][(size_t)M_ * DIN];   // fp16 layer outputs (+x)
__device__ __align__(16) __half g_wh[(size_t)NL * 2 * DIN * NG]; // fp16 W
__device__ float g_h2[2][2][NREG][UN * B_];            // tagged h (fp32), replicated

// ---------------- small helpers --------------------------------------------
__device__ __forceinline__ float sigm(float x) {
    return 1.0f / (1.0f + __expf(-x));
}
__device__ __forceinline__ void cp16(void* s, const void* g) {
    unsigned a = (unsigned)__cvta_generic_to_shared(s);
    asm volatile("cp.async.cg.shared.global [%0], [%1], 16;" :: "r"(a), "l"(g));
}
__device__ __forceinline__ void cp_commit() {
    asm volatile("cp.async.commit_group;" ::: "memory");
}
__device__ __forceinline__ void cp_wait1() {
    asm volatile("cp.async.wait_group 1;" ::: "memory");
}
__device__ __forceinline__ float4 ldv4_vol(const float4* p) {
    float4 v;
    asm volatile("ld.volatile.global.v4.f32 {%0,%1,%2,%3}, [%4];"
                 : "=f"(v.x), "=f"(v.y), "=f"(v.z), "=f"(v.w) : "l"(p) : "memory");
    return v;
}
__device__ __forceinline__ void st_vol(float* p, float v) {
    asm volatile("st.volatile.global.f32 [%0], %1;" :: "l"(p), "f"(v) : "memory");
}

// ---------------- fp16 pre-conversion (once per launch) ---------------------
__global__ void to_half(const float* __restrict__ in, __half* __restrict__ out,
                        size_t n4) {
    size_t i = (size_t)blockIdx.x * blockDim.x + threadIdx.x;
    size_t stride = (size_t)gridDim.x * blockDim.x;
    for (; i < n4; i += stride) {
        float4 v = ((const float4*)in)[i];
        __half2 a = __floats2half2_rn(v.x, v.y);
        __half2 b = __floats2half2_rn(v.z, v.w);
        *(uint2*)&out[i * 4] = make_uint2(*(unsigned*)&a, *(unsigned*)&b);
    }
}

// ---------------- input-projection GEMM (fp16 wmma, 3-stage cp.async) ------
// C[M_, NG] = A[M_, DIN] @ W[DIN, NG] + bias ; grid.z = direction
#define BM 128
#define BN 128
#define BK 32
#define APH 40    // As leading dim (halfs): 80B
#define BPH 136   // Bs leading dim (halfs): 272B
#define ASZH (BM * APH)       // halfs per A stage
#define BSZH (BK * BPH)       // halfs per B stage
#define STAGE_H (ASZH + BSZH) // 9472 halfs = 18944 B
#define GEMM_SMEM (3 * STAGE_H * 2 + 16 * BPH * 4)  // 65536 B

__global__ void __launch_bounds__(256, 2) lstm_gemm(const __half* __restrict__ A,
                                                    const __half* __restrict__ Wl,
                                                    const float* __restrict__ bl) {
    extern __shared__ char gsm[];
    __half* stg = (__half*)gsm;                       // 3 stages of A+B
    float* Bias = (float*)(gsm + 3 * STAGE_H * 2);    // 16 x BPH fp32

    const int d = blockIdx.z;
    const __half* W = Wl + (size_t)d * DIN * NG;
    const float* bias = bl + d * NG;
    float* C = g_xz[d];

    const int tid = threadIdx.x;
    const int bn0 = blockIdx.x * BN;
    const int bm0 = blockIdx.y * BM;

    for (int i = tid; i < 16 * BN; i += 256) {
        int r = i >> 7, c = i & 127;
        Bias[r * BPH + c] = bias[bn0 + c];
    }

    const int wid = tid >> 5;
    const int wr = wid >> 2;   // 0..1 -> 64-row slab
    const int wc = wid & 3;    // 0..3 -> 32-col slab

    const __half* Abase = A + (size_t)bm0 * DIN;
    const __half* Bbase = W + bn0;

    auto issue = [&](int kt) {
        int s = kt % 3;
        __half* Ad = stg + s * STAGE_H;
        __half* Bd = Ad + ASZH;
        const __half* Ag = Abase + kt * BK;
        // A: 128 rows x 32 halfs = 4 chunks/row, 512 chunks
        {
            int id = tid;           // 2 per thread
            int r = id >> 2, ch = (id & 3) << 3;
            cp16(&Ad[r * APH + ch], &Ag[(size_t)r * DIN + ch]);
            id += 256;
            r = id >> 2; ch = (id & 3) << 3;
            cp16(&Ad[r * APH + ch], &Ag[(size_t)r * DIN + ch]);
        }
        const __half* Bg = Bbase + (size_t)kt * BK * NG;
        // B: 32 rows x 128 halfs = 16 chunks/row, 512 chunks
        {
            int id = tid;
            int r = id >> 4, ch = (id & 15) << 3;
            cp16(&Bd[r * BPH + ch], &Bg[(size_t)r * NG + ch]);
            id += 256;
            r = id >> 4; ch = (id & 15) << 3;
            cp16(&Bd[r * BPH + ch], &Bg[(size_t)r * NG + ch]);
        }
        cp_commit();
    };

    issue(0);
    issue(1);
    __syncthreads();   // Bias visible

    wmma::fragment<wmma::accumulator, 16, 16, 16, float> acc[4][2];
#pragma unroll
    for (int mm = 0; mm < 4; ++mm)
#pragma unroll
        for (int nn = 0; nn < 2; ++nn)
            wmma::load_matrix_sync(acc[mm][nn], &Bias[wc * 32 + nn * 16], BPH,
                                   wmma::mem_row_major);

    const int NT = DIN / BK;   // 32
    for (int kt = 0; kt < NT; ++kt) {
        cp_wait1();            // tile kt resident (kt+1 may be in flight)
        __syncthreads();
        if (kt + 2 < NT) issue(kt + 2);

        int s = kt % 3;
        __half* Ab = stg + s * STAGE_H;
        __half* Bb = Ab + ASZH;
#pragma unroll
        for (int kk = 0; kk < 2; ++kk) {
            wmma::fragment<wmma::matrix_a, 16, 16, 16, __half, wmma::row_major> af[4];
            wmma::fragment<wmma::matrix_b, 16, 16, 16, __half, wmma::row_major> bf[2];
#pragma unroll
            for (int mm = 0; mm < 4; ++mm)
                wmma::load_matrix_sync(af[mm], &Ab[(wr * 64 + mm * 16) * APH + kk * 16], APH);
#pragma unroll
            for (int nn = 0; nn < 2; ++nn)
                wmma::load_matrix_sync(bf[nn], &Bb[kk * 16 * BPH + wc * 32 + nn * 16], BPH);
#pragma unroll
            for (int mm = 0; mm < 4; ++mm)
#pragma unroll
                for (int nn = 0; nn < 2; ++nn)
                    wmma::mma_sync(acc[mm][nn], af[mm], bf[nn], acc[mm][nn]);
        }
        __syncthreads();
    }

#pragma unroll
    for (int mm = 0; mm < 4; ++mm)
#pragma unroll
        for (int nn = 0; nn < 2; ++nn)
            wmma::store_matrix_sync(
                &C[(size_t)(bm0 + wr * 64 + mm * 16) * NG + bn0 + wc * 32 + nn * 16],
                acc[mm][nn], NG, wmma::mem_row_major);
}

// ---------------- persistent bidirectional recurrence (fp16 tensor-core) ---
// 128 CTAs: blocks 0..63 dir 0 (fwd), 64..127 dir 1 (rev). CTA owns 8 units.
// Tagged-h transport (fp32, raw h + phase offset), fp16 MMA (m16n16k16).
#define OFF_HS   0                       // half[512*16]        16384 B
#define OFF_RED  16384                   // float[2][8][512]    32768 B (col-major ldm16)
#define OFF_XZ   49152                   // float[2][16*36]      4608 B
#define OFF_CS   53760                   // float[128]            512 B
#define REC_SMEM 54272                   // Uh fp16 staging (32KB) aliases [0,32K)

__global__ void __launch_bounds__(256, 1) lstm_rec(const float* __restrict__ Uh_l,
                                                   int y_sel, float* __restrict__ out) {
    extern __shared__ char sm[];
    __half* Uh_s = (__half*)(sm);        // init-only staging (aliases h_s + red)
    __half* h_s  = (__half*)(sm + OFF_HS);
    float* red  = (float*)(sm + OFF_RED);
    float* xz_s = (float*)(sm + OFF_XZ);
    float* c_s  = (float*)(sm + OFF_CS);

    const int tid = threadIdx.x;
    const int d = blockIdx.x >> 6;
    const int cb = blockIdx.x & 63;
    const int u0 = cb * 8;
    const int reg = cb >> 3;             // consumer octant -> region
    const int wid = tid >> 5, lane = tid & 31;
    const int k0 = wid << 6;             // 64-wide K chunk per warp

    const float* Uh = Uh_l + (size_t)d * UN * NG;
    const float* xz = g_xz[d];
    const bool final_layer = (y_sel == 2);
    __half* yout_h = (y_sel == 0) ? g_yh[0] : g_yh[1];

    // ---- init: stage Uh (fp16) and load register fragments ----
    for (int i = tid; i < UN * 32; i += 256) {
        int k = i >> 5, c = i & 31;
        int g = c >> 3, j = c & 7;
        Uh_s[i] = __float2half_rn(Uh[(size_t)k * NG + g * UN + u0 + j]);
    }
    __syncthreads();

    wmma::fragment<wmma::matrix_b, 16, 16, 16, __half, wmma::row_major> bfr[4][2];
#pragma unroll
    for (int ks = 0; ks < 4; ++ks)
#pragma unroll
        for (int nt = 0; nt < 2; ++nt)
            wmma::load_matrix_sync(bfr[ks][nt], &Uh_s[(k0 + ks * 16) * 32 + nt * 16], 32);
    __syncthreads();

    // publish hin_0 = zeros (tag 2.0) into all regions; c = 0
    if (tid < 128) {
        c_s[tid] = 0.0f;
        int ul = tid >> 4, b = tid & 15;
        float* base = &g_h2[d][0][0][(u0 + ul) * B_ + b];
#pragma unroll
        for (int r = 0; r < NREG; ++r) st_vol(base + r * (UN * B_), 2.0f);
    }
    __syncthreads();

    for (int step = 0; step < T_; ++step) {
        const int tt = d ? (T_ - 1 - step) : step;
        const int p = step & 1;
        const float e  = 2.0f + 2.0f * (float)((step >> 1) & 1);
        const float e1 = e + 1.0f;       // inclusive (h can round to 1.0)

        // 1) xz for this timestep -> regs
        float2 xv;
        {
            int b = tid >> 4, q = tid & 15;
            int c = q << 1, g = c >> 3, j = c & 7;
            xv = *(const float2*)&xz[((size_t)(b << 10) + tt) * NG + g * UN + u0 + j];
        }

        // 2) per-warp: spin-load own 64x16 h slice from own region
        float4 v[8];
        {
            const float4* src = (const float4*)(g_h2[d][p][reg]) + k0 * 4;
            unsigned done = 0;
            while (done != 0xFFu) {
#pragma unroll
                for (int i = 0; i < 8; ++i)
                    if (!((done >> i) & 1)) v[i] = ldv4_vol(src + lane + i * 32);
#pragma unroll
                for (int i = 0; i < 8; ++i)
                    if (!((done >> i) & 1)) {
                        bool ok = (v[i].x >= e) & (v[i].x <= e1) &
                                  (v[i].y >= e) & (v[i].y <= e1) &
                                  (v[i].z >= e) & (v[i].z <= e1) &
                                  (v[i].w >= e) & (v[i].w <= e1);
                        if (ok) done |= 1u << i;
                    }
            }
            // deswizzle -> fp16 smem [k][b] (col-major A, ldm 16)
#pragma unroll
            for (int i = 0; i < 8; ++i) {
                int idx = k0 * 4 + lane + i * 32;     // float4 index over [unit][b]
                int k = idx >> 2, q4 = idx & 3;
                __half2 p0 = __floats2half2_rn(v[i].x - e, v[i].y - e);
                __half2 p1 = __floats2half2_rn(v[i].z - e, v[i].w - e);
                __half2* dst = (__half2*)&h_s[k * 16 + q4 * 4];
                dst[0] = p0;
                dst[1] = p1;
            }
            __syncwarp();
        }

        // 3) xz -> smem buffer p
        {
            int b = tid >> 4, c = (tid & 15) << 1;
            *(float2*)&xz_s[p * 576 + b * 36 + c] = xv;
        }

        // 4) per-warp fp16 MMA over its 64-wide K chunk; col-major store
        {
            wmma::fragment<wmma::accumulator, 16, 16, 16, float> a0a, a0b, a1a, a1b;
            wmma::fill_fragment(a0a, 0.0f); wmma::fill_fragment(a0b, 0.0f);
            wmma::fill_fragment(a1a, 0.0f); wmma::fill_fragment(a1b, 0.0f);
#pragma unroll
            for (int ks = 0; ks < 4; ks += 2) {
                wmma::fragment<wmma::matrix_a, 16, 16, 16, __half, wmma::col_major> af0, af1;
                wmma::load_matrix_sync(af0, &h_s[(k0 + ks * 16) * 16], 16);
                wmma::load_matrix_sync(af1, &h_s[(k0 + (ks + 1) * 16) * 16], 16);
                wmma::mma_sync(a0a, af0, bfr[ks][0], a0a);
                wmma::mma_sync(a1a, af0, bfr[ks][1], a1a);
                wmma::mma_sync(a0b, af1, bfr[ks + 1][0], a0b);
                wmma::mma_sync(a1b, af1, bfr[ks + 1][1], a1b);
            }
#pragma unroll
            for (int i = 0; i < a0a.num_elements; ++i) {
                a0a.x[i] += a0b.x[i];
                a1a.x[i] += a1b.x[i];
            }
            float* rb = &red[(p * 8 + wid) * 512];
            wmma::store_matrix_sync(rb, a0a, 16, wmma::mem_col_major);
            wmma::store_matrix_sync(rb + 256, a1a, 16, wmma::mem_col_major);
        }
        __syncthreads();   // the ONLY barrier per step

        // 5) fused reduce + gates + publish (warps 0-3)
        if (tid < 128) {
            int ul = tid >> 4, b = tid & 15;
            float v0 = xz_s[p * 576 + b * 36 + 0 * 8 + ul];
            float v1 = xz_s[p * 576 + b * 36 + 1 * 8 + ul];
            float v2 = xz_s[p * 576 + b * 36 + 2 * 8 + ul];
            float v3 = xz_s[p * 576 + b * 36 + 3 * 8 + ul];
#pragma unroll
            for (int w = 0; w < 8; ++w) {
                const float* rb = &red[(p * 8 + w) * 512];
                v0 += rb[(0 * 8 + ul) * 16 + b];
                v1 += rb[(1 * 8 + ul) * 16 + b];
                v2 += rb[(2 * 8 + ul) * 16 + b];
                v3 += rb[(3 * 8 + ul) * 16 + b];
            }
            float cc = sigm(v1) * c_s[tid] + sigm(v0) * sigm(v2);
            c_s[tid] = cc;
            float h = sigm(v3) * sigm(cc);
            if (step < T_ - 1) {
                float tv = h + 2.0f + 2.0f * (float)(((step + 1) >> 1) & 1);
                float* base = &g_h2[d][(step + 1) & 1][0][(u0 + ul) * B_ + b];
#pragma unroll
                for (int r = 0; r < NREG; ++r) st_vol(base + r * (UN * B_), tv);
            }
            size_t yidx = ((size_t)(b << 10) + tt) * (2 * UN) + (d << 9) + u0 + ul;
            if (final_layer) out[yidx] = h;
            else             yout_h[yidx] = __float2half_rn(h);
        }
        // red/xz double-buffered; h_s warp-private; no trailing barrier
    }
}

// ---------------- launcher ---------------------------------------------------
extern "C" void kernel_launch(void* const* d_in, const int* in_sizes, int n_in,
                              void* d_out, int out_size) {
    (void)in_sizes; (void)n_in; (void)out_size;
    const float* x  = (const float*)d_in[0];
    const float* W  = (const float*)d_in[1];
    const float* Uh = (const float*)d_in[2];
    const float* bb = (const float*)d_in[3];
    float* out = (float*)d_out;

    cudaFuncSetAttribute(lstm_gemm, cudaFuncAttributeMaxDynamicSharedMemorySize, GEMM_SMEM);
    cudaFuncSetAttribute(lstm_rec,  cudaFuncAttributeMaxDynamicSharedMemorySize, REC_SMEM);

    __half* g_yh_p; cudaGetSymbolAddress((void**)&g_yh_p, g_yh);
    __half* g_wh_p; cudaGetSymbolAddress((void**)&g_wh_p, g_wh);
    __half* xh = g_yh_p + (size_t)M_ * DIN;   // g_yh[1] holds fp16 x
    to_half<<<1024, 256>>>(x, xh, (size_t)M_ * DIN / 4);
    to_half<<<2048, 256>>>(W, g_wh_p, (size_t)NL * 2 * DIN * NG / 4);

    dim3 ggrid(NG / BN, M_ / BM, 2);
    for (int l = 0; l < NL; ++l) {
        const __half* A = (l == 0) ? xh : (g_yh_p + (size_t)((l & 1) ^ 1) * M_ * DIN);
        lstm_gemm<<<ggrid, 256, GEMM_SMEM>>>(A,
                                             g_wh_p + (size_t)l * 2 * DIN * NG,
                                             bb + (size_t)l * 2 * NG);
        int y_sel = (l == NL - 1) ? 2 : (l & 1);
        lstm_rec<<<128, 256, REC_SMEM>>>(Uh + (size_t)l * 2 * UN * NG, y_sel, out);
    }
}